// round 14
// baseline (speedup 1.0000x reference)
#include <cuda_runtime.h>
#include <cuda_fp16.h>
#include <cstdint>

// out[b,o] = ( x @ softmax(W,axis=1)^T > 0.5 )
// Two-pass: (1) HMMA fp16 two-limb GEMM (scale 2^16, fp32 accum) decides all
// outputs with |S1 - 32768| > 0.6 (provably matches the reference fp32 serial
// chain); (2) ambiguous outputs (~3.4k) replay the exact serial ascending-k
// fp32 FMA chain. VALIDATED R12/R13: rel_err 4.888245e-4 (1 flip).
// R14: GEMM loads via cp.async double-buffer (kills STS stall tail);
//      cleanup: 512 blocks + double-buffered staging.

#define M_DIM 4096
#define N_DIM 2048
#define K_DIM 2048

#define SCALE_F 65536.0f
#define THRESH_S 32768.0f
#define AMB_S 0.6f
#define CAP 65536

__device__ float  g_w[(size_t)N_DIM * K_DIM];
__device__ __half g_xh[(size_t)M_DIM * K_DIM];
__device__ __half g_h1[(size_t)N_DIM * K_DIM];
__device__ __half g_h2[(size_t)N_DIM * K_DIM];
__device__ int g_cnt;
__device__ int g_list[CAP];

// ===================== kernel 0: x -> fp16, reset counter =====================
__global__ __launch_bounds__(256) void xconv_kernel(const float* __restrict__ x) {
    if (blockIdx.x == 0 && threadIdx.x == 0) g_cnt = 0;
    const size_t i = ((size_t)blockIdx.x * 256 + threadIdx.x) * 8;
    const float4 v0 = *(const float4*)(x + i);
    const float4 v1 = *(const float4*)(x + i + 4);
    __half2 h[4];
    h[0] = __floats2half2_rn(v0.x, v0.y);
    h[1] = __floats2half2_rn(v0.z, v0.w);
    h[2] = __floats2half2_rn(v1.x, v1.y);
    h[3] = __floats2half2_rn(v1.z, v1.w);
    *(uint4*)(g_xh + i) = *(const uint4*)h;
}

// ===================== kernel 1: XLA softmax replica + limbs =====================
__global__ __launch_bounds__(1024) void softmax_rows_kernel(const float* __restrict__ raw) {
    const int row = blockIdx.x;
    const int tid = threadIdx.x;
    const int lane = tid & 31;
    const int wid = tid >> 5;

    const float2* __restrict__ r2 =
        reinterpret_cast<const float2*>(raw + (size_t)row * K_DIM);
    float2* __restrict__ w2 = reinterpret_cast<float2*>(g_w + (size_t)row * K_DIM);

    const float2 v = r2[tid];

    __shared__ float s_part[32];
    __shared__ float s_bcast;

    float m = fmaxf(v.x, v.y);
#pragma unroll
    for (int off = 16; off > 0; off >>= 1)
        m = fmaxf(m, __shfl_down_sync(0xffffffffu, m, off));
    if (lane == 0) s_part[wid] = m;
    __syncthreads();
    if (wid == 0) {
        float t = s_part[lane];
#pragma unroll
        for (int off = 16; off > 0; off >>= 1)
            t = fmaxf(t, __shfl_down_sync(0xffffffffu, t, off));
        if (lane == 0) s_bcast = t;
    }
    __syncthreads();
    m = s_bcast;
    __syncthreads();

    const float e0 = expf(v.x - m);
    const float e1 = expf(v.y - m);

    float p = e0 + e1;
#pragma unroll
    for (int off = 16; off > 0; off >>= 1)
        p += __shfl_down_sync(0xffffffffu, p, off);
    if (lane == 0) s_part[wid] = p;
    __syncthreads();
    if (wid == 0) {
        float t = s_part[lane];
#pragma unroll
        for (int off = 16; off > 0; off >>= 1)
            t += __shfl_down_sync(0xffffffffu, t, off);
        if (lane == 0) s_bcast = t;
    }
    __syncthreads();
    const float S = s_bcast;

    float2 w;
    w.x = e0 / S;
    w.y = e1 / S;
    w2[tid] = w;

    const float tx = w.x * SCALE_F;
    const float ty = w.y * SCALE_F;
    const __half ax = __float2half_rn(tx);
    const __half ay = __float2half_rn(ty);
    const __half bx = __float2half_rn(tx - __half2float(ax));
    const __half by = __float2half_rn(ty - __half2float(ay));
    reinterpret_cast<__half2*>(g_h1 + (size_t)row * K_DIM)[tid] = __halves2half2(ax, ay);
    reinterpret_cast<__half2*>(g_h2 + (size_t)row * K_DIM)[tid] = __halves2half2(bx, by);
}

// ===================== kernel 2: HMMA two-limb GEMM (cp.async) ================
#define SROW 24
#define TILE_H (128 * SROW)
#define NKT (K_DIM / 16)

__device__ __forceinline__ uint32_t smem_u32(const void* p) {
    uint32_t a;
    asm("{ .reg .u64 t; cvta.to.shared.u64 t, %1; cvt.u32.u64 %0, t; }" : "=r"(a) : "l"(p));
    return a;
}

#define CP16(dst, src) \
    asm volatile("cp.async.cg.shared.global [%0], [%1], 16;" :: "r"(dst), "l"(src))
#define CP_COMMIT() asm volatile("cp.async.commit_group;" ::: "memory")
#define CP_WAIT1()  asm volatile("cp.async.wait_group 1;" ::: "memory")
#define CP_WAIT0()  asm volatile("cp.async.wait_group 0;" ::: "memory")

#define LDSM_X4(r0, r1, r2, r3, a) \
    asm volatile("ldmatrix.sync.aligned.m8n8.x4.shared.b16 {%0,%1,%2,%3}, [%4];" \
                 : "=r"(r0), "=r"(r1), "=r"(r2), "=r"(r3) : "r"(a))
#define LDSM_X2(r0, r1, a) \
    asm volatile("ldmatrix.sync.aligned.m8n8.x2.shared.b16 {%0,%1}, [%2];" \
                 : "=r"(r0), "=r"(r1) : "r"(a))
#define MMA16816(c, a0, a1, a2, a3, b0, b1)                                    \
    asm volatile(                                                              \
        "mma.sync.aligned.m16n8k16.row.col.f32.f16.f16.f32 "                   \
        "{%0,%1,%2,%3}, {%4,%5,%6,%7}, {%8,%9}, {%0,%1,%2,%3};"                \
        : "+f"(c[0]), "+f"(c[1]), "+f"(c[2]), "+f"(c[3])                       \
        : "r"(a0), "r"(a1), "r"(a2), "r"(a3), "r"(b0), "r"(b1))

__global__ __launch_bounds__(256, 2) void mma_gemm_kernel(float* __restrict__ C) {
    __shared__ __half sm[2 * 3 * TILE_H];  // [buf][A/B1/B2][tile]

    const int tid = threadIdx.x;
    const int wid = tid >> 5;
    const int lane = tid & 31;
    const int wm = wid & 1;
    const int wn = wid >> 1;
    const int bm = blockIdx.y * 128;
    const int bn = blockIdx.x * 128;

    const int lrow = tid >> 1;
    const int lc = (tid & 1) * 8;
    const uint32_t ldst_b = (uint32_t)(lrow * SROW + lc) * 2;  // byte offset in tile

    const __half* __restrict__ Ag = g_xh + (size_t)(bm + lrow) * K_DIM + lc;
    const __half* __restrict__ B1g = g_h1 + (size_t)(bn + lrow) * K_DIM + lc;
    const __half* __restrict__ B2g = g_h2 + (size_t)(bn + lrow) * K_DIM + lc;

    const int a_off = (wm * 64 + (lane & 15)) * SROW + (lane >> 4) * 8;
    const int b_off = (wn * 32 + (lane & 7)) * SROW + ((lane >> 3) & 1) * 8;

    const uint32_t sm0 = smem_u32(sm);
    const uint32_t TB = (uint32_t)TILE_H * 2;  // tile bytes

    float c[16][4];
#pragma unroll
    for (int f = 0; f < 16; ++f)
#pragma unroll
        for (int u = 0; u < 4; ++u) c[f][u] = 0.f;

    // prologue: async-load chunk 0 into buf 0
    CP16(sm0 + 0 * TB + ldst_b, Ag);
    CP16(sm0 + 1 * TB + ldst_b, B1g);
    CP16(sm0 + 2 * TB + ldst_b, B2g);
    CP_COMMIT();

    int buf = 0;
    for (int kt = 0; kt < NKT; ++kt) {
        const bool has_next = (kt + 1 < NKT);
        if (has_next) {
            const int ko = (kt + 1) * 16;
            const uint32_t nb = sm0 + (uint32_t)(buf ^ 1) * (3 * TB);
            CP16(nb + 0 * TB + ldst_b, Ag + ko);
            CP16(nb + 1 * TB + ldst_b, B1g + ko);
            CP16(nb + 2 * TB + ldst_b, B2g + ko);
            CP_COMMIT();
            CP_WAIT1();   // chunk kt complete (only kt+1 group may remain)
        } else {
            CP_WAIT0();
        }
        __syncthreads();  // cross-thread visibility of chunk kt

        const uint32_t base = sm0 + (uint32_t)buf * (3 * TB);
        uint32_t a[4][4];
#pragma unroll
        for (int mi = 0; mi < 4; ++mi)
            LDSM_X4(a[mi][0], a[mi][1], a[mi][2], a[mi][3],
                    base + (uint32_t)(a_off + mi * 16 * SROW) * 2);
        uint32_t b1[4][2], b2[4][2];
#pragma unroll
        for (int ni = 0; ni < 4; ++ni) {
            LDSM_X2(b1[ni][0], b1[ni][1], base + TB + (uint32_t)(b_off + ni * 8 * SROW) * 2);
            LDSM_X2(b2[ni][0], b2[ni][1], base + 2 * TB + (uint32_t)(b_off + ni * 8 * SROW) * 2);
        }

#pragma unroll
        for (int mi = 0; mi < 4; ++mi)
#pragma unroll
            for (int ni = 0; ni < 4; ++ni)
                MMA16816(c[mi * 4 + ni], a[mi][0], a[mi][1], a[mi][2], a[mi][3],
                         b1[ni][0], b1[ni][1]);
#pragma unroll
        for (int mi = 0; mi < 4; ++mi)
#pragma unroll
            for (int ni = 0; ni < 4; ++ni)
                MMA16816(c[mi * 4 + ni], a[mi][0], a[mi][1], a[mi][2], a[mi][3],
                         b2[ni][0], b2[ni][1]);

        __syncthreads();  // compute done before buf is overwritten next iter
        buf ^= 1;
    }

    const int gl = lane >> 2;
    const int tg = lane & 3;
#pragma unroll
    for (int mi = 0; mi < 4; ++mi) {
#pragma unroll
        for (int ni = 0; ni < 4; ++ni) {
            const float* cc = c[mi * 4 + ni];
            const int r0 = bm + wm * 64 + mi * 16 + gl;
            const int n0 = bn + wn * 32 + ni * 8 + tg * 2;
#pragma unroll
            for (int h = 0; h < 2; ++h) {
                const int r = r0 + h * 8;
                const float v0 = cc[h * 2 + 0];
                const float v1 = cc[h * 2 + 1];
                if (fabsf(v0 - THRESH_S) < AMB_S) {
                    const int ix = atomicAdd(&g_cnt, 1);
                    if (ix < CAP) g_list[ix] = r * N_DIM + n0;
                }
                if (fabsf(v1 - THRESH_S) < AMB_S) {
                    const int ix = atomicAdd(&g_cnt, 1);
                    if (ix < CAP) g_list[ix] = r * N_DIM + n0 + 1;
                }
                float2 o;
                o.x = v0 > THRESH_S ? 1.f : 0.f;
                o.y = v1 > THRESH_S ? 1.f : 0.f;
                *(float2*)&C[(size_t)r * N_DIM + n0] = o;
            }
        }
    }
}

// ===================== kernel 3: warp-cooperative exact cleanup ================
// One warp per ambiguous output; 256-element chunks, double-buffered staging:
// lanes prefetch chunk c+1 while lane 0 replays the serial chain on chunk c.
#define CCH 256

__global__ __launch_bounds__(256) void cleanup_kernel(const float* __restrict__ x,
                                                      float* __restrict__ C) {
    __shared__ float sw[8][2][CCH];
    __shared__ float sx[8][2][CCH];

    int n = g_cnt;
    if (n > CAP) n = CAP;

    const int warp = threadIdx.x >> 5;
    const int lane = threadIdx.x & 31;
    const int gw = blockIdx.x * 8 + warp;
    const int nw = gridDim.x * 8;

    for (int t = gw; t < n; t += nw) {
        const int id = g_list[t];
        const int b = id >> 11;
        const int o = id & (N_DIM - 1);
        const float* __restrict__ xr = x + (size_t)b * K_DIM;
        const float* __restrict__ wr = g_w + (size_t)o * K_DIM;

        // stage chunk 0
#pragma unroll
        for (int i = 0; i < CCH / 128; ++i) {
            const int idx = (lane + i * 32) * 4;
            *(float4*)&sw[warp][0][idx] = *(const float4*)&wr[idx];
            *(float4*)&sx[warp][0][idx] = *(const float4*)&xr[idx];
        }
        __syncwarp();

        float acc = 0.f;
#pragma unroll
        for (int cc = 0; cc < K_DIM / CCH; ++cc) {
            if (cc + 1 < K_DIM / CCH) {
                const int c0 = (cc + 1) * CCH;
#pragma unroll
                for (int i = 0; i < CCH / 128; ++i) {
                    const int idx = (lane + i * 32) * 4;
                    *(float4*)&sw[warp][(cc + 1) & 1][idx] = *(const float4*)&wr[c0 + idx];
                    *(float4*)&sx[warp][(cc + 1) & 1][idx] = *(const float4*)&xr[c0 + idx];
                }
            }
            if (lane == 0) {
                const float* swp = sw[warp][cc & 1];
                const float* sxp = sx[warp][cc & 1];
#pragma unroll 16
                for (int k = 0; k < CCH; ++k)  // strictly ascending serial chain
                    acc = fmaf(sxp[k], swp[k], acc);
            }
            __syncwarp();
        }
        if (lane == 0) C[id] = acc > 0.5f ? 1.f : 0.f;
    }
}

// ---------------------------------------------------------------------------
extern "C" void kernel_launch(void* const* d_in, const int* in_sizes, int n_in,
                              void* d_out, int out_size) {
    const float* x = (const float*)d_in[0];      // [4096, 2048]
    const float* raw_w = (const float*)d_in[1];  // [2048, 2048]
    float* out = (float*)d_out;                  // [4096, 2048]

    xconv_kernel<<<(M_DIM * K_DIM) / (256 * 8), 256>>>(x);
    softmax_rows_kernel<<<N_DIM, 1024>>>(raw_w);

    dim3 grid(N_DIM / 128, M_DIM / 128);  // (16, 32)
    mma_gemm_kernel<<<grid, 256>>>(out);

    cleanup_kernel<<<512, 256>>>(x, out);
}

// round 15
// speedup vs baseline: 1.0998x; 1.0998x over previous
#include <cuda_runtime.h>
#include <cuda_fp16.h>
#include <cstdint>

// out[b,o] = ( x @ softmax(W,axis=1)^T > 0.5 )
// Two-pass: (1) HMMA fp16 two-limb GEMM (scale 2^16, fp32 accum) decides all
// outputs with |S1 - 32768| > 0.6 (provably matches the reference fp32 serial
// chain); (2) ambiguous outputs (~3.4k) replay the exact serial ascending-k
// fp32 FMA chain. VALIDATED R12-R14: rel_err 4.888245e-4 (1 flip).
// R15: GEMM = 4-stage cp.async ring (1 barrier/k-step, 3-chunk load lead);
//      cleanup = one block per output, full-row smem staging (max MLP).

#define M_DIM 4096
#define N_DIM 2048
#define K_DIM 2048

#define SCALE_F 65536.0f
#define THRESH_S 32768.0f
#define AMB_S 0.6f
#define CAP 65536

__device__ float  g_w[(size_t)N_DIM * K_DIM];
__device__ __half g_xh[(size_t)M_DIM * K_DIM];
__device__ __half g_h1[(size_t)N_DIM * K_DIM];
__device__ __half g_h2[(size_t)N_DIM * K_DIM];
__device__ int g_cnt;
__device__ int g_list[CAP];

// ===================== kernel 0: x -> fp16, reset counter =====================
__global__ __launch_bounds__(256) void xconv_kernel(const float* __restrict__ x) {
    if (blockIdx.x == 0 && threadIdx.x == 0) g_cnt = 0;
    const size_t i = ((size_t)blockIdx.x * 256 + threadIdx.x) * 8;
    const float4 v0 = *(const float4*)(x + i);
    const float4 v1 = *(const float4*)(x + i + 4);
    __half2 h[4];
    h[0] = __floats2half2_rn(v0.x, v0.y);
    h[1] = __floats2half2_rn(v0.z, v0.w);
    h[2] = __floats2half2_rn(v1.x, v1.y);
    h[3] = __floats2half2_rn(v1.z, v1.w);
    *(uint4*)(g_xh + i) = *(const uint4*)h;
}

// ===================== kernel 1: XLA softmax replica + limbs =====================
__global__ __launch_bounds__(1024) void softmax_rows_kernel(const float* __restrict__ raw) {
    const int row = blockIdx.x;
    const int tid = threadIdx.x;
    const int lane = tid & 31;
    const int wid = tid >> 5;

    const float2* __restrict__ r2 =
        reinterpret_cast<const float2*>(raw + (size_t)row * K_DIM);
    float2* __restrict__ w2 = reinterpret_cast<float2*>(g_w + (size_t)row * K_DIM);

    const float2 v = r2[tid];

    __shared__ float s_part[32];
    __shared__ float s_bcast;

    float m = fmaxf(v.x, v.y);
#pragma unroll
    for (int off = 16; off > 0; off >>= 1)
        m = fmaxf(m, __shfl_down_sync(0xffffffffu, m, off));
    if (lane == 0) s_part[wid] = m;
    __syncthreads();
    if (wid == 0) {
        float t = s_part[lane];
#pragma unroll
        for (int off = 16; off > 0; off >>= 1)
            t = fmaxf(t, __shfl_down_sync(0xffffffffu, t, off));
        if (lane == 0) s_bcast = t;
    }
    __syncthreads();
    m = s_bcast;
    __syncthreads();

    const float e0 = expf(v.x - m);
    const float e1 = expf(v.y - m);

    float p = e0 + e1;
#pragma unroll
    for (int off = 16; off > 0; off >>= 1)
        p += __shfl_down_sync(0xffffffffu, p, off);
    if (lane == 0) s_part[wid] = p;
    __syncthreads();
    if (wid == 0) {
        float t = s_part[lane];
#pragma unroll
        for (int off = 16; off > 0; off >>= 1)
            t += __shfl_down_sync(0xffffffffu, t, off);
        if (lane == 0) s_bcast = t;
    }
    __syncthreads();
    const float S = s_bcast;

    float2 w;
    w.x = e0 / S;
    w.y = e1 / S;
    w2[tid] = w;

    const float tx = w.x * SCALE_F;
    const float ty = w.y * SCALE_F;
    const __half ax = __float2half_rn(tx);
    const __half ay = __float2half_rn(ty);
    const __half bx = __float2half_rn(tx - __half2float(ax));
    const __half by = __float2half_rn(ty - __half2float(ay));
    reinterpret_cast<__half2*>(g_h1 + (size_t)row * K_DIM)[tid] = __halves2half2(ax, ay);
    reinterpret_cast<__half2*>(g_h2 + (size_t)row * K_DIM)[tid] = __halves2half2(bx, by);
}

// ===================== kernel 2: HMMA two-limb GEMM, 4-stage cp.async ========
#define SROW 24
#define TILE_H (128 * SROW)
#define TB ((uint32_t)TILE_H * 2)   // tile bytes: 6144
#define STB (3 * TB)                // stage bytes (A,B1,B2): 18432
#define NSTAGE 4
#define SMEM_DYN (NSTAGE * STB)     // 73728
#define NKT (K_DIM / 16)            // 128

__device__ __forceinline__ uint32_t smem_u32(const void* p) {
    uint32_t a;
    asm("{ .reg .u64 t; cvta.to.shared.u64 t, %1; cvt.u32.u64 %0, t; }" : "=r"(a) : "l"(p));
    return a;
}

#define CP16(dst, src) \
    asm volatile("cp.async.cg.shared.global [%0], [%1], 16;" :: "r"(dst), "l"(src))
#define CP_COMMIT() asm volatile("cp.async.commit_group;" ::: "memory")
#define CP_WAIT2()  asm volatile("cp.async.wait_group 2;" ::: "memory")
#define CP_WAIT1()  asm volatile("cp.async.wait_group 1;" ::: "memory")
#define CP_WAIT0()  asm volatile("cp.async.wait_group 0;" ::: "memory")

#define LDSM_X4(r0, r1, r2, r3, a) \
    asm volatile("ldmatrix.sync.aligned.m8n8.x4.shared.b16 {%0,%1,%2,%3}, [%4];" \
                 : "=r"(r0), "=r"(r1), "=r"(r2), "=r"(r3) : "r"(a))
#define LDSM_X2(r0, r1, a) \
    asm volatile("ldmatrix.sync.aligned.m8n8.x2.shared.b16 {%0,%1}, [%2];" \
                 : "=r"(r0), "=r"(r1) : "r"(a))
#define MMA16816(c, a0, a1, a2, a3, b0, b1)                                    \
    asm volatile(                                                              \
        "mma.sync.aligned.m16n8k16.row.col.f32.f16.f16.f32 "                   \
        "{%0,%1,%2,%3}, {%4,%5,%6,%7}, {%8,%9}, {%0,%1,%2,%3};"                \
        : "+f"(c[0]), "+f"(c[1]), "+f"(c[2]), "+f"(c[3])                       \
        : "r"(a0), "r"(a1), "r"(a2), "r"(a3), "r"(b0), "r"(b1))

__global__ __launch_bounds__(256, 2) void mma_gemm_kernel(float* __restrict__ C) {
    extern __shared__ __half dsm[];

    const int tid = threadIdx.x;
    const int wid = tid >> 5;
    const int lane = tid & 31;
    const int wm = wid & 1;
    const int wn = wid >> 1;
    const int bm = blockIdx.y * 128;
    const int bn = blockIdx.x * 128;

    const int lrow = tid >> 1;
    const int lc = (tid & 1) * 8;
    const uint32_t ldst_b = (uint32_t)(lrow * SROW + lc) * 2;

    const __half* __restrict__ Ag = g_xh + (size_t)(bm + lrow) * K_DIM + lc;
    const __half* __restrict__ B1g = g_h1 + (size_t)(bn + lrow) * K_DIM + lc;
    const __half* __restrict__ B2g = g_h2 + (size_t)(bn + lrow) * K_DIM + lc;

    const int a_off = (wm * 64 + (lane & 15)) * SROW + (lane >> 4) * 8;
    const int b_off = (wn * 32 + (lane & 7)) * SROW + ((lane >> 3) & 1) * 8;

    const uint32_t sm0 = smem_u32(dsm);

    float c[16][4];
#pragma unroll
    for (int f = 0; f < 16; ++f)
#pragma unroll
        for (int u = 0; u < 4; ++u) c[f][u] = 0.f;

    // prologue: async-load chunks 0,1,2 into stages 0,1,2
#pragma unroll
    for (int p = 0; p < NSTAGE - 1; ++p) {
        const uint32_t sbase = sm0 + (uint32_t)p * STB;
        const int ko = p * 16;
        CP16(sbase + 0 * TB + ldst_b, Ag + ko);
        CP16(sbase + 1 * TB + ldst_b, B1g + ko);
        CP16(sbase + 2 * TB + ldst_b, B2g + ko);
        CP_COMMIT();
    }

    for (int kt = 0; kt < NKT; ++kt) {
        // retire chunk kt (pending groups before wait: kt..kt+2 at most)
        if (kt < NKT - 2) { CP_WAIT2(); }
        else if (kt == NKT - 2) { CP_WAIT1(); }
        else { CP_WAIT0(); }
        __syncthreads();  // chunk kt visible; compute of kt-1 retired everywhere

        // refill stage (kt+3)&3 (held chunk kt-1, now dead)
        if (kt + 3 < NKT) {
            const uint32_t sbase = sm0 + (uint32_t)((kt + 3) & 3) * STB;
            const int ko = (kt + 3) * 16;
            CP16(sbase + 0 * TB + ldst_b, Ag + ko);
            CP16(sbase + 1 * TB + ldst_b, B1g + ko);
            CP16(sbase + 2 * TB + ldst_b, B2g + ko);
            CP_COMMIT();
        }

        const uint32_t base = sm0 + (uint32_t)(kt & 3) * STB;
        uint32_t a[4][4];
#pragma unroll
        for (int mi = 0; mi < 4; ++mi)
            LDSM_X4(a[mi][0], a[mi][1], a[mi][2], a[mi][3],
                    base + (uint32_t)(a_off + mi * 16 * SROW) * 2);
        uint32_t b1[4][2], b2[4][2];
#pragma unroll
        for (int ni = 0; ni < 4; ++ni) {
            LDSM_X2(b1[ni][0], b1[ni][1], base + TB + (uint32_t)(b_off + ni * 8 * SROW) * 2);
            LDSM_X2(b2[ni][0], b2[ni][1], base + 2 * TB + (uint32_t)(b_off + ni * 8 * SROW) * 2);
        }

#pragma unroll
        for (int mi = 0; mi < 4; ++mi)
#pragma unroll
            for (int ni = 0; ni < 4; ++ni)
                MMA16816(c[mi * 4 + ni], a[mi][0], a[mi][1], a[mi][2], a[mi][3],
                         b1[ni][0], b1[ni][1]);
#pragma unroll
        for (int mi = 0; mi < 4; ++mi)
#pragma unroll
            for (int ni = 0; ni < 4; ++ni)
                MMA16816(c[mi * 4 + ni], a[mi][0], a[mi][1], a[mi][2], a[mi][3],
                         b2[ni][0], b2[ni][1]);
    }

    const int gl = lane >> 2;
    const int tg = lane & 3;
#pragma unroll
    for (int mi = 0; mi < 4; ++mi) {
#pragma unroll
        for (int ni = 0; ni < 4; ++ni) {
            const float* cc = c[mi * 4 + ni];
            const int r0 = bm + wm * 64 + mi * 16 + gl;
            const int n0 = bn + wn * 32 + ni * 8 + tg * 2;
#pragma unroll
            for (int h = 0; h < 2; ++h) {
                const int r = r0 + h * 8;
                const float v0 = cc[h * 2 + 0];
                const float v1 = cc[h * 2 + 1];
                if (fabsf(v0 - THRESH_S) < AMB_S) {
                    const int ix = atomicAdd(&g_cnt, 1);
                    if (ix < CAP) g_list[ix] = r * N_DIM + n0;
                }
                if (fabsf(v1 - THRESH_S) < AMB_S) {
                    const int ix = atomicAdd(&g_cnt, 1);
                    if (ix < CAP) g_list[ix] = r * N_DIM + n0 + 1;
                }
                float2 o;
                o.x = v0 > THRESH_S ? 1.f : 0.f;
                o.y = v1 > THRESH_S ? 1.f : 0.f;
                *(float2*)&C[(size_t)r * N_DIM + n0] = o;
            }
        }
    }
}

// ===================== kernel 3: block-per-output exact cleanup ================
// 256 threads stage full w and x rows (4 float4/thread in flight each);
// thread 0 replays the exact serial ascending-k fp32 FMA chain from smem.
__global__ __launch_bounds__(256) void cleanup_kernel(const float* __restrict__ x,
                                                      float* __restrict__ C) {
    __shared__ float sw[K_DIM];
    __shared__ float sx[K_DIM];

    int n = g_cnt;
    if (n > CAP) n = CAP;
    const int tid = threadIdx.x;

    for (int t = blockIdx.x; t < n; t += gridDim.x) {
        const int id = g_list[t];
        const int b = id >> 11;             // N_DIM = 2048
        const int o = id & (N_DIM - 1);
        const float4* __restrict__ xr = (const float4*)(x + (size_t)b * K_DIM);
        const float4* __restrict__ wr = (const float4*)(g_w + (size_t)o * K_DIM);

#pragma unroll
        for (int i = 0; i < 2; ++i) {
            const int idx = tid + i * 256;   // 512 float4 per row
            ((float4*)sx)[idx] = xr[idx];
            ((float4*)sw)[idx] = wr[idx];
        }
        __syncthreads();
        if (tid == 0) {
            float acc = 0.f;
#pragma unroll 16
            for (int k = 0; k < K_DIM; ++k)  // strictly ascending serial chain
                acc = fmaf(sx[k], sw[k], acc);
            C[id] = acc > 0.5f ? 1.f : 0.f;
        }
        __syncthreads();
    }
}

// ---------------------------------------------------------------------------
extern "C" void kernel_launch(void* const* d_in, const int* in_sizes, int n_in,
                              void* d_out, int out_size) {
    const float* x = (const float*)d_in[0];      // [4096, 2048]
    const float* raw_w = (const float*)d_in[1];  // [2048, 2048]
    float* out = (float*)d_out;                  // [4096, 2048]

    // idempotent attribute set (host-side, not a stream op; capture-safe)
    cudaFuncSetAttribute(mma_gemm_kernel,
                         cudaFuncAttributeMaxDynamicSharedMemorySize, SMEM_DYN);

    xconv_kernel<<<(M_DIM * K_DIM) / (256 * 8), 256>>>(x);
    softmax_rows_kernel<<<N_DIM, 1024>>>(raw_w);

    dim3 grid(N_DIM / 128, M_DIM / 128);  // (16, 32)
    mma_gemm_kernel<<<grid, 256, SMEM_DYN>>>(out);

    cleanup_kernel<<<2048, 256>>>(x, out);
}